// round 4
// baseline (speedup 1.0000x reference)
#include <cuda_runtime.h>

// Problem constants
#define Bn   64
#define Rn   4608
#define Cn   32
#define INn  8
#define OUTn 16
#define RCHUNK 64
#define NCHUNK 72    // Rn / RCHUNK

typedef unsigned long long ull;

// Scratch (device globals; allocation-free per harness rules)
static __device__ float4 g_xT4[(size_t)Rn * 2 * Bn];               // x transposed: [r][h][b] float4
static __device__ float  g_red[(size_t)Cn * NCHUNK * Bn * 17];     // pass partials (n[16], d)
static __device__ float  g_v1[(size_t)Bn * Cn * OUTn];
static __device__ float  g_vcur[(size_t)Bn * Cn * OUTn];           // logit vector (zero-init; iter1 ignores)

// ---- packed f32x2 helpers ----
__device__ __forceinline__ ull pk2(float lo, float hi) {
    ull r;
    asm("mov.b64 %0, {%1, %2};" : "=l"(r) : "f"(lo), "f"(hi));
    return r;
}
__device__ __forceinline__ ull ffma2(ull a, ull b, ull c) {
    ull d;
    asm("fma.rn.f32x2 %0, %1, %2, %3;" : "=l"(d) : "l"(a), "l"(b), "l"(c));
    return d;
}
__device__ __forceinline__ float2 upk2(ull v) {
    float lo, hi;
    asm("mov.b64 {%0, %1}, %2;" : "=f"(lo), "=f"(hi) : "l"(v));
    return make_float2(lo, hi);
}

// ============================================================================
// k0: transpose x (64 b, 9216 float4-cols) -> xT (9216 rows, 64 b).
// ============================================================================
__global__ void __launch_bounds__(256)
k0_transpose(const float4* __restrict__ x4) {
    __shared__ float4 tile[32][33];
    const int f0 = blockIdx.x * 32;
    const int b0 = blockIdx.y * 32;
    const int tx = threadIdx.x;
    const int ty0 = threadIdx.y;
    #pragma unroll
    for (int j = 0; j < 4; j++) {
        int ty = ty0 * 4 + j;
        tile[ty][tx] = x4[(size_t)(b0 + ty) * (Rn * 2) + f0 + tx];
    }
    __syncthreads();
    #pragma unroll
    for (int j = 0; j < 4; j++) {
        int ty = ty0 * 4 + j;
        g_xT4[(size_t)(f0 + ty) * Bn + b0 + tx] = tile[tx][ty];
    }
}

// ============================================================================
// kpass: one routing pass with u recomputed on the fly (no u_hat tensor).
// Grid (Cn, NCHUNK). Block 256 = 4 r-groups x 64 batches (lane = batch).
// W chunk staged in smem (broadcast LDS.128). x from transposed L2-hot buffer.
// mode 0: e = 1 (iteration-1 plain sum). mode 1: e = exp(u . v).
// Per-thread (d, n[16]) accumulators; fixed-order reduction -> deterministic.
// ============================================================================
__global__ void __launch_bounds__(256, 2)
kpass(int mode, const float* __restrict__ w) {
    const int c     = blockIdx.x;
    const int chunk = blockIdx.y;
    const int r0    = chunk * RCHUNK;
    const int tid   = threadIdx.x;

    __shared__ float sW[RCHUNK * 128];   // 32 KB: W[r0..r0+63][c][i][o]; reused for reduction
    __shared__ float sV[Bn * OUTn];      // 4 KB: current v per batch

    // Stage W chunk (coalesced float4)
    {
        const float4* wg = reinterpret_cast<const float4*>(w);
        float4*       ws = reinterpret_cast<float4*>(sW);
        #pragma unroll
        for (int t = tid; t < RCHUNK * 32; t += 256) {
            int rr = t >> 5;
            int q  = t & 31;
            ws[rr * 32 + q] = wg[((size_t)(r0 + rr) * Cn + c) * 32 + q];
        }
    }
    // Stage v (g_vcur is zero for mode 0 -> t=0, unused)
    for (int t = tid; t < Bn * OUTn; t += 256) {
        int b_ = t >> 4, o_ = t & 15;
        sV[t] = g_vcur[((size_t)b_ * Cn + c) * OUTn + o_];
    }
    __syncthreads();

    const int rg = tid >> 6;       // 0..3 (16 routes each)
    const int b  = tid & 63;       // batch (lane-contiguous -> dense x loads)

    float v[OUTn];
    #pragma unroll
    for (int o = 0; o < OUTn; o++) v[o] = sV[b * OUTn + o];

    float d = 0.f;
    float n[OUTn];
    #pragma unroll
    for (int o = 0; o < OUTn; o++) n[o] = 0.f;

    #pragma unroll 2
    for (int k = 0; k < RCHUNK / 4; k++) {
        const int rr = rg * (RCHUNK / 4) + k;
        const int r  = r0 + rr;

        // x row (8 floats), dense across lanes, L2-resident
        float4 xa = g_xT4[((size_t)r * 2 + 0) * Bn + b];
        float4 xb = g_xT4[((size_t)r * 2 + 1) * Bn + b];
        float xv[8] = {xa.x, xa.y, xa.z, xa.w, xb.x, xb.y, xb.z, xb.w};

        // u = W_r^T x  (8 f32x2 accumulators = 16 outputs)
        ull acc[8];
        #pragma unroll
        for (int jp = 0; jp < 8; jp++) acc[jp] = 0ull;

        const ulonglong2* wr =
            reinterpret_cast<const ulonglong2*>(sW + rr * 128);
        #pragma unroll
        for (int i = 0; i < 8; i++) {
            ull x2 = pk2(xv[i], xv[i]);
            #pragma unroll
            for (int jq = 0; jq < 4; jq++) {
                ulonglong2 p = wr[i * 4 + jq];     // broadcast LDS.128
                acc[2 * jq]     = ffma2(x2, p.x, acc[2 * jq]);
                acc[2 * jq + 1] = ffma2(x2, p.y, acc[2 * jq + 1]);
            }
        }

        float u[OUTn];
        #pragma unroll
        for (int jp = 0; jp < 8; jp++) {
            float2 f = upk2(acc[jp]);
            u[2 * jp]     = f.x;
            u[2 * jp + 1] = f.y;
        }

        float t = 0.f;
        #pragma unroll
        for (int o = 0; o < OUTn; o++) t = fmaf(u[o], v[o], t);
        float e = mode ? __expf(t) : 1.0f;   // logits bounded; no max-sub needed
        d += e;
        #pragma unroll
        for (int o = 0; o < OUTn; o++) n[o] = fmaf(e, u[o], n[o]);
    }

    // ---- reduce (n[16], d) over the 4 r-groups; write per-(c,chunk,b) ----
    __syncthreads();                 // done with sW contents
    float* sred = sW;                // [4 rg][64 b][17] = 17.4 KB
    float* sr = sred + ((size_t)rg * Bn + b) * 17;
    #pragma unroll
    for (int o = 0; o < OUTn; o++) sr[o] = n[o];
    sr[16] = d;
    __syncthreads();

    for (int t = tid; t < Bn * 17; t += 256) {
        int b_ = t / 17, o_ = t % 17;
        float s = sred[((0 * Bn + b_)) * 17 + o_]
                + sred[((1 * Bn + b_)) * 17 + o_]
                + sred[((2 * Bn + b_)) * 17 + o_]
                + sred[((3 * Bn + b_)) * 17 + o_];
        g_red[(((size_t)c * NCHUNK + chunk) * Bn + b_) * 17 + o_] = s;
    }
}

// ============================================================================
// kf_v1: v1 = squash(mean_r u_r) from pass-0 partials; seeds g_vcur = v1.
// ============================================================================
__global__ void __launch_bounds__(32)
kf_v1() {
    const int bc = blockIdx.x;
    const int b  = bc >> 5;
    const int c  = bc & 31;
    const int t  = threadIdx.x;

    float acc = 0.f;
    if (t < OUTn) {
        for (int ch = 0; ch < NCHUNK; ch++)
            acc += g_red[(((size_t)c * NCHUNK + ch) * Bn + b) * 17 + t];
    }
    float val = (t < OUTn) ? acc * (1.0f / Rn) : 0.f;
    float sq = val * val;
    #pragma unroll
    for (int off = 16; off; off >>= 1) sq += __shfl_xor_sync(0xffffffffu, sq, off);
    float coef = (sq / (1.f + sq)) * rsqrtf(sq + 1e-8f);
    float v = val * coef;
    if (t < OUTn) {
        g_v1[(size_t)bc * OUTn + t]   = v;
        g_vcur[(size_t)bc * OUTn + t] = v;
    }
}

// ============================================================================
// kf_fin: reduce chunk partials -> softmax-weighted sum -> squash.
// mode 0: g_vcur = v1 + v2 (logits for pass 3).  mode 1: write v3 to out.
// ============================================================================
__global__ void __launch_bounds__(32)
kf_fin(int mode, float* __restrict__ out) {
    const int bc = blockIdx.x;
    const int b  = bc >> 5;
    const int c  = bc & 31;
    const int t  = threadIdx.x;

    float acc = 0.f;
    if (t < 17) {
        for (int ch = 0; ch < NCHUNK; ch++)
            acc += g_red[(((size_t)c * NCHUNK + ch) * Bn + b) * 17 + t];
    }
    float D = __shfl_sync(0xffffffffu, acc, 16);
    float val = (t < OUTn) ? acc / D : 0.f;
    float sq = val * val;
    #pragma unroll
    for (int off = 16; off; off >>= 1) sq += __shfl_xor_sync(0xffffffffu, sq, off);
    float coef = (sq / (1.f + sq)) * rsqrtf(sq + 1e-8f);
    float v = val * coef;
    if (t < OUTn) {
        if (mode == 0)
            g_vcur[(size_t)bc * OUTn + t] = g_v1[(size_t)bc * OUTn + t] + v;
        else
            out[(size_t)bc * OUTn + t] = v;
    }
}

// ============================================================================
extern "C" void kernel_launch(void* const* d_in, const int* in_sizes, int n_in,
                              void* d_out, int out_size) {
    const float* x = (const float*)d_in[0];           // (64, 4608, 8)
    const float* w = (const float*)d_in[1];           // (4608, 32, 8, 16)
    float* out = (float*)d_out;                       // (64, 32, 16)

    dim3 gp(Cn, NCHUNK);
    k0_transpose<<<dim3(Rn * 2 / 32, Bn / 32), dim3(32, 8)>>>((const float4*)x);
    kpass<<<gp, 256>>>(0, w);          // iteration 1 (e = 1)
    kf_v1<<<Bn * Cn, 32>>>();
    kpass<<<gp, 256>>>(1, w);          // iteration 2
    kf_fin<<<Bn * Cn, 32>>>(0, out);
    kpass<<<gp, 256>>>(1, w);          // iteration 3
    kf_fin<<<Bn * Cn, 32>>>(1, out);
}